// round 14
// baseline (speedup 1.0000x reference)
#include <cuda_runtime.h>
#include <cuda_fp16.h>
#include <cstdint>

#define NREL 8
#define F    128
#define NMAX 100000
#define EMAX 1600000
#define NBUCK (NMAX * NREL)

// Scratch (no allocation allowed)
__device__ __align__(16) __half g_Hh[(size_t)NREL * NMAX * F];  // 204.8 MB
__device__ __align__(16) __half g_wh[NREL * F * F];  // transposed: [r][n][k]
__device__ int g_cnt[NBUCK + 1];   // histogram -> block-local offsets -> local ends
__device__ int g_eidx[EMAX];       // src per edge, bucket-sorted
__device__ int g_bsum[1024];       // per-1024-chunk base offsets
__device__ int g_done;             // last-block ticket (re-zeroed every launch)

// ---------------------------------------------------------------------------
// Fused setup: zero histogram + ticket, weight [r][k][n] -> fp16 [r][n][k]
// ---------------------------------------------------------------------------
__global__ void setup_kernel(const float* __restrict__ wgt, int n_w, int nb) {
    int i = blockIdx.x * blockDim.x + threadIdx.x;
    if (i < n_w) {
        int r = i >> 14, rem = i & 16383, k = rem >> 7, nn = rem & 127;
        g_wh[r * 16384 + nn * 128 + k] = __float2half_rn(wgt[i]);
    }
    if (i <= nb) g_cnt[i] = 0;
    if (i == 0) g_done = 0;
}

// ---------------------------------------------------------------------------
// Counting sort by key = et*n_nodes + dst; 4 edges per thread for atomic MLP.
// ---------------------------------------------------------------------------
__global__ void hist_kernel(const int* __restrict__ dst,
                            const int* __restrict__ et, int E, int n_nodes) {
    int i = (blockIdx.x * blockDim.x + threadIdx.x) * 4;
    if (i + 3 < E) {
        int4 d = *reinterpret_cast<const int4*>(dst + i);
        int4 t = *reinterpret_cast<const int4*>(et + i);
        atomicAdd(&g_cnt[t.x * n_nodes + d.x], 1);
        atomicAdd(&g_cnt[t.y * n_nodes + d.y], 1);
        atomicAdd(&g_cnt[t.z * n_nodes + d.z], 1);
        atomicAdd(&g_cnt[t.w * n_nodes + d.w], 1);
    } else {
        for (int e = i; e < E; e++)
            atomicAdd(&g_cnt[et[e] * n_nodes + dst[e]], 1);
    }
}

// Per-block exclusive scan in place; block totals -> g_bsum; the LAST block
// to finish also scans g_bsum in place (fused scan2).
__global__ void __launch_bounds__(1024) scan1_kernel(int n) {
    const int tid = threadIdx.x, lane = tid & 31, wid = tid >> 5;
    __shared__ int wsum[32];
    __shared__ int s_last;
    int i = blockIdx.x * 1024 + tid;
    int x = (i < n) ? g_cnt[i] : 0;
    int v = x;
#pragma unroll
    for (int d = 1; d < 32; d <<= 1) {
        int t = __shfl_up_sync(0xFFFFFFFFu, v, d);
        if (lane >= d) v += t;
    }
    if (lane == 31) wsum[wid] = v;
    __syncthreads();
    if (wid == 0) {
        int s = wsum[lane];
        int sv = s;
#pragma unroll
        for (int d = 1; d < 32; d <<= 1) {
            int t = __shfl_up_sync(0xFFFFFFFFu, sv, d);
            if (lane >= d) sv += t;
        }
        wsum[lane] = sv - s;
    }
    __syncthreads();
    if (i < n) g_cnt[i] = wsum[wid] + v - x;   // block-local exclusive
    if (tid == 1023) g_bsum[blockIdx.x] = wsum[31] + v;
    __threadfence();
    __syncthreads();
    if (tid == 0) s_last = (atomicAdd(&g_done, 1) == (int)gridDim.x - 1);
    __syncthreads();
    if (s_last) {  // fused scan2: exclusive scan of g_bsum[0..gridDim.x)
        int nblk = (int)gridDim.x;
        int bx = (tid < nblk) ? g_bsum[tid] : 0;
        int bv = bx;
#pragma unroll
        for (int d = 1; d < 32; d <<= 1) {
            int t = __shfl_up_sync(0xFFFFFFFFu, bv, d);
            if (lane >= d) bv += t;
        }
        __syncthreads();
        if (lane == 31) wsum[wid] = bv;
        __syncthreads();
        if (wid == 0) {
            int s = wsum[lane];
            int sv = s;
#pragma unroll
            for (int d = 1; d < 32; d <<= 1) {
                int t = __shfl_up_sync(0xFFFFFFFFu, sv, d);
                if (lane >= d) sv += t;
            }
            wsum[lane] = sv - s;
        }
        __syncthreads();
        if (tid < nblk) g_bsum[tid] = wsum[wid] + bv - bx;
    }
}

// Fill: final position = local atomicAdd + chunk base; 4 edges per thread.
__global__ void fill_kernel(const int* __restrict__ src,
                            const int* __restrict__ dst,
                            const int* __restrict__ et, int E, int n_nodes) {
    int i = (blockIdx.x * blockDim.x + threadIdx.x) * 4;
    if (i + 3 < E) {
        int4 s = *reinterpret_cast<const int4*>(src + i);
        int4 d = *reinterpret_cast<const int4*>(dst + i);
        int4 t = *reinterpret_cast<const int4*>(et + i);
        int k0 = t.x * n_nodes + d.x, k1 = t.y * n_nodes + d.y;
        int k2 = t.z * n_nodes + d.z, k3 = t.w * n_nodes + d.w;
        int p0 = atomicAdd(&g_cnt[k0], 1) + g_bsum[k0 >> 10];
        int p1 = atomicAdd(&g_cnt[k1], 1) + g_bsum[k1 >> 10];
        int p2 = atomicAdd(&g_cnt[k2], 1) + g_bsum[k2 >> 10];
        int p3 = atomicAdd(&g_cnt[k3], 1) + g_bsum[k3 >> 10];
        g_eidx[p0] = s.x; g_eidx[p1] = s.y; g_eidx[p2] = s.z; g_eidx[p3] = s.w;
    } else {
        for (int e = i; e < E; e++) {
            int key = et[e] * n_nodes + dst[e];
            int p = atomicAdd(&g_cnt[key], 1) + g_bsum[key >> 10];
            g_eidx[p] = src[e];
        }
    }
}

// ---------------------------------------------------------------------------
// Aggregate: one warp per 8 CONSECUTIVE buckets (contiguous edge range).
// Flattened range streamed in chunks of 8 -> 8 feat loads in flight.
// Warp-uniform boundary branches route rows to the right accumulator.
// ---------------------------------------------------------------------------
__global__ void aggregate_kernel(const float* __restrict__ feat, int nb) {
    int w = (blockIdx.x * blockDim.x + threadIdx.x) >> 5;
    int lane = threadIdx.x & 31;
    int base = w * 8;
    if (base >= nb) return;

    // lane-parallel bounds: lane l in 0..8 loads end(base-1+l); end(-1)=0
    int kk = base - 1 + lane;
    int bnd = 0;
    if (lane < 9 && kk >= 0) bnd = g_cnt[kk] + g_bsum[kk >> 10];
    int e0 = __shfl_sync(0xFFFFFFFFu, bnd, 0);
    int e1 = __shfl_sync(0xFFFFFFFFu, bnd, 1);
    int e2 = __shfl_sync(0xFFFFFFFFu, bnd, 2);
    int e3 = __shfl_sync(0xFFFFFFFFu, bnd, 3);
    int e4 = __shfl_sync(0xFFFFFFFFu, bnd, 4);
    int e5 = __shfl_sync(0xFFFFFFFFu, bnd, 5);
    int e6 = __shfl_sync(0xFFFFFFFFu, bnd, 6);
    int e7 = __shfl_sync(0xFFFFFFFFu, bnd, 7);
    int e8 = __shfl_sync(0xFFFFFFFFu, bnd, 8);

    float4 a0 = make_float4(0.f, 0.f, 0.f, 0.f);
    float4 a1 = a0, a2 = a0, a3 = a0, a4 = a0, a5 = a0, a6 = a0, a7 = a0;

    for (int c = e0; c < e8; c += 8) {
        int s[8];
#pragma unroll
        for (int t = 0; t < 8; t++)
            s[t] = (c + t < e8) ? g_eidx[c + t] : -1;
        float4 f[8];
#pragma unroll
        for (int t = 0; t < 8; t++)
            f[t] = (s[t] >= 0)
                ? reinterpret_cast<const float4*>(feat + (size_t)s[t] * F)[lane]
                : make_float4(0.f, 0.f, 0.f, 0.f);
#pragma unroll
        for (int t = 0; t < 8; t++) {
            int j = c + t;
            if (j >= e8) break;           // warp-uniform
            float4 v = f[t];
            if (j < e1)      { a0.x += v.x; a0.y += v.y; a0.z += v.z; a0.w += v.w; }
            else if (j < e2) { a1.x += v.x; a1.y += v.y; a1.z += v.z; a1.w += v.w; }
            else if (j < e3) { a2.x += v.x; a2.y += v.y; a2.z += v.z; a2.w += v.w; }
            else if (j < e4) { a3.x += v.x; a3.y += v.y; a3.z += v.z; a3.w += v.w; }
            else if (j < e5) { a4.x += v.x; a4.y += v.y; a4.z += v.z; a4.w += v.w; }
            else if (j < e6) { a5.x += v.x; a5.y += v.y; a5.z += v.z; a5.w += v.w; }
            else if (j < e7) { a6.x += v.x; a6.y += v.y; a6.z += v.z; a6.w += v.w; }
            else             { a7.x += v.x; a7.y += v.y; a7.z += v.z; a7.w += v.w; }
        }
    }

    // write 8 consecutive H rows (fp16) = 2 KB contiguous per warp
#pragma unroll
    for (int i = 0; i < 8; i++) {
        float4 a = (i == 0) ? a0 : (i == 1) ? a1 : (i == 2) ? a2 : (i == 3) ? a3
                 : (i == 4) ? a4 : (i == 5) ? a5 : (i == 6) ? a6 : a7;
        __half2 h01 = __halves2half2(__float2half_rn(a.x), __float2half_rn(a.y));
        __half2 h23 = __halves2half2(__float2half_rn(a.z), __float2half_rn(a.w));
        uint2 u;
        u.x = *reinterpret_cast<uint32_t*>(&h01);
        u.y = *reinterpret_cast<uint32_t*>(&h23);
        *reinterpret_cast<uint2*>(g_Hh + (size_t)(base + i) * F + lane * 4) = u;
    }
}

// ---------------------------------------------------------------------------
// Legacy-pipe GEMM building blocks
// ---------------------------------------------------------------------------
__device__ __forceinline__ uint32_t smem_u32(const void* p) {
    uint32_t a;
    asm("{ .reg .u64 t; cvta.to.shared.u64 t, %1; cvt.u32.u64 %0, t; }" : "=r"(a) : "l"(p));
    return a;
}

__device__ __forceinline__ void mma16816(float c[4], const uint32_t a[4],
                                         const uint32_t b0, const uint32_t b1) {
    asm volatile(
        "mma.sync.aligned.m16n8k16.row.col.f32.f16.f16.f32 "
        "{%0,%1,%2,%3}, {%4,%5,%6,%7}, {%8,%9}, {%0,%1,%2,%3};"
        : "+f"(c[0]), "+f"(c[1]), "+f"(c[2]), "+f"(c[3])
        : "r"(a[0]), "r"(a[1]), "r"(a[2]), "r"(a[3]), "r"(b0), "r"(b1));
}

#define LDSM_X4(r, addr) \
    asm volatile("ldmatrix.sync.aligned.m8n8.x4.shared.b16 {%0,%1,%2,%3}, [%4];" \
                 : "=r"((r)[0]), "=r"((r)[1]), "=r"((r)[2]), "=r"((r)[3]) : "r"(addr))

#define PITCH_B 272
#define TILE_SZ (128 * PITCH_B)   // 34816 B

__device__ __forceinline__ void cpa_tile(uint32_t s_base, const __half* g,
                                         int valid_rows, int tid) {
    const char* gc = reinterpret_cast<const char*>(g);
#pragma unroll
    for (int it = 0; it < 4; it++) {
        int i = tid + it * 512;
        int m = i >> 4, c = i & 15;
        uint32_t s = s_base + m * PITCH_B + c * 16;
        const char* src = gc + m * 256 + c * 16;
        int sz = (m < valid_rows) ? 16 : 0;
        asm volatile("cp.async.cg.shared.global [%0], [%1], 16, %2;"
                     :: "r"(s), "l"(src), "r"(sz) : "memory");
    }
}

// SMEM map: A x2 buffers, B x2 buffers
#define OFF_A0 0u
#define OFF_A1 34816u
#define OFF_B0 69632u
#define OFF_B1 104448u
#define SMEM_SZ 139264

// ---------------------------------------------------------------------------
// GEMM: per CTA one 128-row dst tile; loop 8 relations with A=H_r, B=W_r;
// accumulate across relations in registers; write out once.
// ---------------------------------------------------------------------------
__global__ void __launch_bounds__(512, 1) gemm_kernel(float* __restrict__ out,
                                                      int n_nodes) {
    extern __shared__ __align__(128) char smem[];
    const uint32_t sb = smem_u32(smem);
    const int tid = threadIdx.x, wid = tid >> 5, lane = tid & 31;
    const int m0 = blockIdx.x * 128;
    const int valid = n_nodes - m0;

    // Prologue: relation 0 into buffer 0
    cpa_tile(sb + OFF_A0, g_Hh + (size_t)m0 * F, valid, tid);
    cpa_tile(sb + OFF_B0, g_wh, 128, tid);
    asm volatile("cp.async.commit_group;" ::: "memory");

    const int wm = (wid >> 1) * 16;
    const int wn = (wid & 1) * 64;
    const uint32_t a_off =
        (uint32_t)((wm + (lane & 15)) * PITCH_B + ((lane >> 4) * 8) * 2);
    const int b_row = (lane & 7) + ((lane >> 3) & 1) * 8;
    const uint32_t b_koff = (uint32_t)(((lane >> 4) * 8) * 2);

    float acc[8][4];
#pragma unroll
    for (int i = 0; i < 8; i++)
#pragma unroll
        for (int j = 0; j < 4; j++) acc[i][j] = 0.f;

    for (int q = 0; q < NREL; q++) {
        if (q < 7) {  // prefetch next relation into the other buffer
            const int nb1 = (q + 1) & 1;
            cpa_tile(sb + (nb1 ? OFF_A1 : OFF_A0),
                     g_Hh + ((size_t)(q + 1) * n_nodes + m0) * F, valid, tid);
            cpa_tile(sb + (nb1 ? OFF_B1 : OFF_B0),
                     g_wh + (size_t)(q + 1) * F * F, 128, tid);
            asm volatile("cp.async.commit_group;" ::: "memory");
            asm volatile("cp.async.wait_group 1;" ::: "memory");
        } else {
            asm volatile("cp.async.wait_group 0;" ::: "memory");
        }
        __syncthreads();

        const uint32_t ab = sb + ((q & 1) ? OFF_A1 : OFF_A0);
        const uint32_t bb = sb + ((q & 1) ? OFF_B1 : OFF_B0);

#pragma unroll
        for (int kk = 0; kk < 8; kk++) {
            const uint32_t k2 = (uint32_t)(kk * 32);
            uint32_t ah[4];
            LDSM_X4(ah, ab + a_off + k2);
#pragma unroll
            for (int nb = 0; nb < 4; nb++) {
                const uint32_t baddr =
                    bb + (uint32_t)((wn + nb * 16 + b_row) * PITCH_B) + b_koff + k2;
                uint32_t bh[4];
                LDSM_X4(bh, baddr);
                mma16816(acc[nb * 2],     ah, bh[0], bh[2]);
                mma16816(acc[nb * 2 + 1], ah, bh[1], bh[3]);
            }
        }
        __syncthreads();  // all warps done with buf (q&1) before refill
    }

    // Epilogue: single write of the relation-summed tile
    const int r0 = wm + (lane >> 2);
    const bool ok0 = (m0 + r0) < n_nodes;
    const bool ok1 = (m0 + r0 + 8) < n_nodes;
    float* cp = out + (size_t)m0 * F;
#pragma unroll
    for (int ns = 0; ns < 8; ns++) {
        const int col = wn + ns * 8 + (lane & 3) * 2;
        if (ok0) *(float2*)&cp[(size_t)r0 * F + col] =
            make_float2(acc[ns][0], acc[ns][1]);
        if (ok1) *(float2*)&cp[(size_t)(r0 + 8) * F + col] =
            make_float2(acc[ns][2], acc[ns][3]);
    }
}

// ---------------------------------------------------------------------------
extern "C" void kernel_launch(void* const* d_in, const int* in_sizes, int n_in,
                              void* d_out, int out_size) {
    const float* feat   = (const float*)d_in[0];
    const float* weight = (const float*)d_in[1];
    const int*   src    = (const int*)d_in[2];
    const int*   dst    = (const int*)d_in[3];
    const int*   et     = (const int*)d_in[4];

    const int n_nodes = in_sizes[0] / F;
    const int n_w     = in_sizes[1];
    const int E       = in_sizes[2];
    float* out = (float*)d_out;

    const int nb = n_nodes * NREL;            // 800K buckets
    const int nblk = (nb + 1023) / 1024;      // scan blocks (<=1024)

    // Setup: zero histogram + ticket, fp16 transposed weights
    setup_kernel<<<(nb + 256) / 256, 256>>>(weight, n_w, nb);

    // Counting sort by (et, dst); scan2 fused into scan1's last block
    hist_kernel<<<(E / 4 + 255) / 256, 256>>>(dst, et, E, n_nodes);
    scan1_kernel<<<nblk, 1024>>>(nb);
    fill_kernel<<<(E / 4 + 255) / 256, 256>>>(src, dst, et, E, n_nodes);

    // Aggregate feat into H rows: 8 consecutive buckets per warp
    aggregate_kernel<<<(nb * 4 + 255) / 256, 256>>>(feat, nb);

    // Fused relation-sum GEMM: out = sum_r H_r @ W_r
    cudaFuncSetAttribute(gemm_kernel,
                         cudaFuncAttributeMaxDynamicSharedMemorySize, SMEM_SZ);
    gemm_kernel<<<(n_nodes + 127) / 128, 512, SMEM_SZ>>>(out, n_nodes);
}

// round 15
// speedup vs baseline: 1.0222x; 1.0222x over previous
#include <cuda_runtime.h>
#include <cuda_fp16.h>
#include <cstdint>

#define NREL 8
#define F    128
#define NMAX 100000
#define EMAX 1600000
#define NBUCK (NMAX * NREL)

// Scratch (no allocation allowed)
__device__ __align__(16) __half g_Hh[(size_t)NREL * NMAX * F];  // 204.8 MB
__device__ __align__(16) __half g_wh[NREL * F * F];  // transposed: [r][n][k]
__device__ int g_cnt[NBUCK + 1];   // histogram -> block-local offsets -> local ends
__device__ int g_eidx[EMAX];       // src per edge, bucket-sorted
__device__ int g_bsum[1024];       // per-1024-chunk base offsets

// ---------------------------------------------------------------------------
// Setup: weight [r][k][n] fp32 -> fp16 transposed [r][n][k]
// (g_cnt zeroing is done by cudaMemsetAsync host-side)
// ---------------------------------------------------------------------------
__global__ void setup_kernel(const float* __restrict__ wgt, int n_w) {
    int i = blockIdx.x * blockDim.x + threadIdx.x;
    if (i < n_w) {
        int r = i >> 14, rem = i & 16383, k = rem >> 7, nn = rem & 127;
        g_wh[r * 16384 + nn * 128 + k] = __float2half_rn(wgt[i]);
    }
}

// ---------------------------------------------------------------------------
// Counting sort by key = et*n_nodes + dst; 8 edges per thread for atomic MLP.
// ---------------------------------------------------------------------------
__global__ void hist_kernel(const int* __restrict__ dst,
                            const int* __restrict__ et, int E, int n_nodes) {
    int i = (blockIdx.x * blockDim.x + threadIdx.x) * 8;
    if (i + 7 < E) {
        int4 d0 = *reinterpret_cast<const int4*>(dst + i);
        int4 d1 = *reinterpret_cast<const int4*>(dst + i + 4);
        int4 t0 = *reinterpret_cast<const int4*>(et + i);
        int4 t1 = *reinterpret_cast<const int4*>(et + i + 4);
        atomicAdd(&g_cnt[t0.x * n_nodes + d0.x], 1);
        atomicAdd(&g_cnt[t0.y * n_nodes + d0.y], 1);
        atomicAdd(&g_cnt[t0.z * n_nodes + d0.z], 1);
        atomicAdd(&g_cnt[t0.w * n_nodes + d0.w], 1);
        atomicAdd(&g_cnt[t1.x * n_nodes + d1.x], 1);
        atomicAdd(&g_cnt[t1.y * n_nodes + d1.y], 1);
        atomicAdd(&g_cnt[t1.z * n_nodes + d1.z], 1);
        atomicAdd(&g_cnt[t1.w * n_nodes + d1.w], 1);
    } else {
        for (int e = i; e < E; e++)
            atomicAdd(&g_cnt[et[e] * n_nodes + dst[e]], 1);
    }
}

// Pass 1: per-block (1024) exclusive scan in place; block totals -> g_bsum
__global__ void __launch_bounds__(1024) scan1_kernel(int n) {
    const int tid = threadIdx.x, lane = tid & 31, wid = tid >> 5;
    __shared__ int wsum[32];
    int i = blockIdx.x * 1024 + tid;
    int x = (i < n) ? g_cnt[i] : 0;
    int v = x;
#pragma unroll
    for (int d = 1; d < 32; d <<= 1) {
        int t = __shfl_up_sync(0xFFFFFFFFu, v, d);
        if (lane >= d) v += t;
    }
    if (lane == 31) wsum[wid] = v;
    __syncthreads();
    if (wid == 0) {
        int s = wsum[lane];
        int sv = s;
#pragma unroll
        for (int d = 1; d < 32; d <<= 1) {
            int t = __shfl_up_sync(0xFFFFFFFFu, sv, d);
            if (lane >= d) sv += t;
        }
        wsum[lane] = sv - s;
    }
    __syncthreads();
    if (i < n) g_cnt[i] = wsum[wid] + v - x;   // block-local exclusive
    if (tid == 1023) g_bsum[blockIdx.x] = wsum[31] + v;
}

// Pass 2: single-block exclusive scan of the <=1024 block totals (in place)
__global__ void __launch_bounds__(1024) scan2_kernel(int nblk) {
    const int tid = threadIdx.x, lane = tid & 31, wid = tid >> 5;
    __shared__ int wsum[32];
    int x = (tid < nblk) ? g_bsum[tid] : 0;
    int v = x;
#pragma unroll
    for (int d = 1; d < 32; d <<= 1) {
        int t = __shfl_up_sync(0xFFFFFFFFu, v, d);
        if (lane >= d) v += t;
    }
    if (lane == 31) wsum[wid] = v;
    __syncthreads();
    if (wid == 0) {
        int s = wsum[lane];
        int sv = s;
#pragma unroll
        for (int d = 1; d < 32; d <<= 1) {
            int t = __shfl_up_sync(0xFFFFFFFFu, sv, d);
            if (lane >= d) sv += t;
        }
        wsum[lane] = sv - s;
    }
    __syncthreads();
    if (tid < nblk) g_bsum[tid] = wsum[wid] + v - x;
}

// Fill: final position = local atomicAdd + chunk base; 8 edges per thread.
// Afterwards g_cnt[k] = block-local inclusive end.
__global__ void fill_kernel(const int* __restrict__ src,
                            const int* __restrict__ dst,
                            const int* __restrict__ et, int E, int n_nodes) {
    int i = (blockIdx.x * blockDim.x + threadIdx.x) * 8;
    if (i + 7 < E) {
        int4 s0 = *reinterpret_cast<const int4*>(src + i);
        int4 s1 = *reinterpret_cast<const int4*>(src + i + 4);
        int4 d0 = *reinterpret_cast<const int4*>(dst + i);
        int4 d1 = *reinterpret_cast<const int4*>(dst + i + 4);
        int4 t0 = *reinterpret_cast<const int4*>(et + i);
        int4 t1 = *reinterpret_cast<const int4*>(et + i + 4);
        int k0 = t0.x * n_nodes + d0.x, k1 = t0.y * n_nodes + d0.y;
        int k2 = t0.z * n_nodes + d0.z, k3 = t0.w * n_nodes + d0.w;
        int k4 = t1.x * n_nodes + d1.x, k5 = t1.y * n_nodes + d1.y;
        int k6 = t1.z * n_nodes + d1.z, k7 = t1.w * n_nodes + d1.w;
        int p0 = atomicAdd(&g_cnt[k0], 1) + g_bsum[k0 >> 10];
        int p1 = atomicAdd(&g_cnt[k1], 1) + g_bsum[k1 >> 10];
        int p2 = atomicAdd(&g_cnt[k2], 1) + g_bsum[k2 >> 10];
        int p3 = atomicAdd(&g_cnt[k3], 1) + g_bsum[k3 >> 10];
        int p4 = atomicAdd(&g_cnt[k4], 1) + g_bsum[k4 >> 10];
        int p5 = atomicAdd(&g_cnt[k5], 1) + g_bsum[k5 >> 10];
        int p6 = atomicAdd(&g_cnt[k6], 1) + g_bsum[k6 >> 10];
        int p7 = atomicAdd(&g_cnt[k7], 1) + g_bsum[k7 >> 10];
        g_eidx[p0] = s0.x; g_eidx[p1] = s0.y; g_eidx[p2] = s0.z; g_eidx[p3] = s0.w;
        g_eidx[p4] = s1.x; g_eidx[p5] = s1.y; g_eidx[p6] = s1.z; g_eidx[p7] = s1.w;
    } else {
        for (int e = i; e < E; e++) {
            int key = et[e] * n_nodes + dst[e];
            int p = atomicAdd(&g_cnt[key], 1) + g_bsum[key >> 10];
            g_eidx[p] = src[e];
        }
    }
}

// ---------------------------------------------------------------------------
// Aggregate: one warp per 4 CONSECUTIVE buckets (contiguous edge range).
// Flattened range streamed in chunks of 8 -> 8 feat loads in flight.
// Warp-uniform boundary branches route rows to the right accumulator.
// ---------------------------------------------------------------------------
__global__ void aggregate_kernel(const float* __restrict__ feat, int nb) {
    int w = (blockIdx.x * blockDim.x + threadIdx.x) >> 5;
    int lane = threadIdx.x & 31;
    int base = w * 4;
    if (base >= nb) return;

    // lane-parallel bounds: lane l in 0..4 loads end(base-1+l); end(-1)=0
    int kk = base - 1 + lane;
    int bnd = 0;
    if (lane < 5 && kk >= 0) bnd = g_cnt[kk] + g_bsum[kk >> 10];
    int e0 = __shfl_sync(0xFFFFFFFFu, bnd, 0);
    int e1 = __shfl_sync(0xFFFFFFFFu, bnd, 1);
    int e2 = __shfl_sync(0xFFFFFFFFu, bnd, 2);
    int e3 = __shfl_sync(0xFFFFFFFFu, bnd, 3);
    int e4 = __shfl_sync(0xFFFFFFFFu, bnd, 4);

    float4 a0 = make_float4(0.f, 0.f, 0.f, 0.f);
    float4 a1 = a0, a2 = a0, a3 = a0;

    for (int c = e0; c < e4; c += 8) {
        int s[8];
#pragma unroll
        for (int t = 0; t < 8; t++)
            s[t] = (c + t < e4) ? g_eidx[c + t] : -1;
        float4 f[8];
#pragma unroll
        for (int t = 0; t < 8; t++)
            f[t] = (s[t] >= 0)
                ? reinterpret_cast<const float4*>(feat + (size_t)s[t] * F)[lane]
                : make_float4(0.f, 0.f, 0.f, 0.f);
#pragma unroll
        for (int t = 0; t < 8; t++) {
            int j = c + t;
            if (j >= e4) break;           // warp-uniform
            float4 v = f[t];
            if (j < e1)      { a0.x += v.x; a0.y += v.y; a0.z += v.z; a0.w += v.w; }
            else if (j < e2) { a1.x += v.x; a1.y += v.y; a1.z += v.z; a1.w += v.w; }
            else if (j < e3) { a2.x += v.x; a2.y += v.y; a2.z += v.z; a2.w += v.w; }
            else             { a3.x += v.x; a3.y += v.y; a3.z += v.z; a3.w += v.w; }
        }
    }

    // write 4 consecutive H rows (fp16)
#pragma unroll
    for (int i = 0; i < 4; i++) {
        float4 a = (i == 0) ? a0 : (i == 1) ? a1 : (i == 2) ? a2 : a3;
        __half2 h01 = __halves2half2(__float2half_rn(a.x), __float2half_rn(a.y));
        __half2 h23 = __halves2half2(__float2half_rn(a.z), __float2half_rn(a.w));
        uint2 u;
        u.x = *reinterpret_cast<uint32_t*>(&h01);
        u.y = *reinterpret_cast<uint32_t*>(&h23);
        *reinterpret_cast<uint2*>(g_Hh + (size_t)(base + i) * F + lane * 4) = u;
    }
}

// ---------------------------------------------------------------------------
// Legacy-pipe GEMM building blocks
// ---------------------------------------------------------------------------
__device__ __forceinline__ uint32_t smem_u32(const void* p) {
    uint32_t a;
    asm("{ .reg .u64 t; cvta.to.shared.u64 t, %1; cvt.u32.u64 %0, t; }" : "=r"(a) : "l"(p));
    return a;
}

__device__ __forceinline__ void mma16816(float c[4], const uint32_t a[4],
                                         const uint32_t b0, const uint32_t b1) {
    asm volatile(
        "mma.sync.aligned.m16n8k16.row.col.f32.f16.f16.f32 "
        "{%0,%1,%2,%3}, {%4,%5,%6,%7}, {%8,%9}, {%0,%1,%2,%3};"
        : "+f"(c[0]), "+f"(c[1]), "+f"(c[2]), "+f"(c[3])
        : "r"(a[0]), "r"(a[1]), "r"(a[2]), "r"(a[3]), "r"(b0), "r"(b1));
}

#define LDSM_X4(r, addr) \
    asm volatile("ldmatrix.sync.aligned.m8n8.x4.shared.b16 {%0,%1,%2,%3}, [%4];" \
                 : "=r"((r)[0]), "=r"((r)[1]), "=r"((r)[2]), "=r"((r)[3]) : "r"(addr))

#define PITCH_B 272
#define TILE_SZ (128 * PITCH_B)   // 34816 B

__device__ __forceinline__ void cpa_tile(uint32_t s_base, const __half* g,
                                         int valid_rows, int tid) {
    const char* gc = reinterpret_cast<const char*>(g);
#pragma unroll
    for (int it = 0; it < 4; it++) {
        int i = tid + it * 512;
        int m = i >> 4, c = i & 15;
        uint32_t s = s_base + m * PITCH_B + c * 16;
        const char* src = gc + m * 256 + c * 16;
        int sz = (m < valid_rows) ? 16 : 0;
        asm volatile("cp.async.cg.shared.global [%0], [%1], 16, %2;"
                     :: "r"(s), "l"(src), "r"(sz) : "memory");
    }
}

// SMEM map: A x2 buffers, B x2 buffers
#define OFF_A0 0u
#define OFF_A1 34816u
#define OFF_B0 69632u
#define OFF_B1 104448u
#define SMEM_SZ 139264

// ---------------------------------------------------------------------------
// GEMM: per CTA one 128-row dst tile; loop 8 relations with A=H_r, B=W_r;
// accumulate across relations in registers; write out once.
// ---------------------------------------------------------------------------
__global__ void __launch_bounds__(512, 1) gemm_kernel(float* __restrict__ out,
                                                      int n_nodes) {
    extern __shared__ __align__(128) char smem[];
    const uint32_t sb = smem_u32(smem);
    const int tid = threadIdx.x, wid = tid >> 5, lane = tid & 31;
    const int m0 = blockIdx.x * 128;
    const int valid = n_nodes - m0;

    // Prologue: relation 0 into buffer 0
    cpa_tile(sb + OFF_A0, g_Hh + (size_t)m0 * F, valid, tid);
    cpa_tile(sb + OFF_B0, g_wh, 128, tid);
    asm volatile("cp.async.commit_group;" ::: "memory");

    const int wm = (wid >> 1) * 16;
    const int wn = (wid & 1) * 64;
    const uint32_t a_off =
        (uint32_t)((wm + (lane & 15)) * PITCH_B + ((lane >> 4) * 8) * 2);
    const int b_row = (lane & 7) + ((lane >> 3) & 1) * 8;
    const uint32_t b_koff = (uint32_t)(((lane >> 4) * 8) * 2);

    float acc[8][4];
#pragma unroll
    for (int i = 0; i < 8; i++)
#pragma unroll
        for (int j = 0; j < 4; j++) acc[i][j] = 0.f;

    for (int q = 0; q < NREL; q++) {
        if (q < 7) {  // prefetch next relation into the other buffer
            const int nb1 = (q + 1) & 1;
            cpa_tile(sb + (nb1 ? OFF_A1 : OFF_A0),
                     g_Hh + ((size_t)(q + 1) * n_nodes + m0) * F, valid, tid);
            cpa_tile(sb + (nb1 ? OFF_B1 : OFF_B0),
                     g_wh + (size_t)(q + 1) * F * F, 128, tid);
            asm volatile("cp.async.commit_group;" ::: "memory");
            asm volatile("cp.async.wait_group 1;" ::: "memory");
        } else {
            asm volatile("cp.async.wait_group 0;" ::: "memory");
        }
        __syncthreads();

        const uint32_t ab = sb + ((q & 1) ? OFF_A1 : OFF_A0);
        const uint32_t bb = sb + ((q & 1) ? OFF_B1 : OFF_B0);

#pragma unroll
        for (int kk = 0; kk < 8; kk++) {
            const uint32_t k2 = (uint32_t)(kk * 32);
            uint32_t ah[4];
            LDSM_X4(ah, ab + a_off + k2);
#pragma unroll
            for (int nb = 0; nb < 4; nb++) {
                const uint32_t baddr =
                    bb + (uint32_t)((wn + nb * 16 + b_row) * PITCH_B) + b_koff + k2;
                uint32_t bh[4];
                LDSM_X4(bh, baddr);
                mma16816(acc[nb * 2],     ah, bh[0], bh[2]);
                mma16816(acc[nb * 2 + 1], ah, bh[1], bh[3]);
            }
        }
        __syncthreads();  // all warps done with buf (q&1) before refill
    }

    // Epilogue: single write of the relation-summed tile
    const int r0 = wm + (lane >> 2);
    const bool ok0 = (m0 + r0) < n_nodes;
    const bool ok1 = (m0 + r0 + 8) < n_nodes;
    float* cp = out + (size_t)m0 * F;
#pragma unroll
    for (int ns = 0; ns < 8; ns++) {
        const int col = wn + ns * 8 + (lane & 3) * 2;
        if (ok0) *(float2*)&cp[(size_t)r0 * F + col] =
            make_float2(acc[ns][0], acc[ns][1]);
        if (ok1) *(float2*)&cp[(size_t)(r0 + 8) * F + col] =
            make_float2(acc[ns][2], acc[ns][3]);
    }
}

// ---------------------------------------------------------------------------
extern "C" void kernel_launch(void* const* d_in, const int* in_sizes, int n_in,
                              void* d_out, int out_size) {
    const float* feat   = (const float*)d_in[0];
    const float* weight = (const float*)d_in[1];
    const int*   src    = (const int*)d_in[2];
    const int*   dst    = (const int*)d_in[3];
    const int*   et     = (const int*)d_in[4];

    const int n_nodes = in_sizes[0] / F;
    const int n_w     = in_sizes[1];
    const int E       = in_sizes[2];
    float* out = (float*)d_out;

    const int nb = n_nodes * NREL;            // 800K buckets
    const int nblk = (nb + 1023) / 1024;      // scan blocks (<=1024)

    // Zero histogram via fast memset path; convert weights in a small kernel
    void* cnt_ptr = nullptr;
    cudaGetSymbolAddress(&cnt_ptr, g_cnt);
    cudaMemsetAsync(cnt_ptr, 0, (size_t)(nb + 1) * sizeof(int));
    setup_kernel<<<(n_w + 255) / 256, 256>>>(weight, n_w);

    // Counting sort by (et, dst)
    hist_kernel<<<(E / 8 + 255) / 256, 256>>>(dst, et, E, n_nodes);
    scan1_kernel<<<nblk, 1024>>>(nb);
    scan2_kernel<<<1, 1024>>>(nblk);
    fill_kernel<<<(E / 8 + 255) / 256, 256>>>(src, dst, et, E, n_nodes);

    // Aggregate feat into H rows: 4 consecutive buckets per warp
    aggregate_kernel<<<(nb * 8 + 255) / 256, 256>>>(feat, nb);

    // Fused relation-sum GEMM: out = sum_r H_r @ W_r
    cudaFuncSetAttribute(gemm_kernel,
                         cudaFuncAttributeMaxDynamicSharedMemorySize, SMEM_SZ);
    gemm_kernel<<<(n_nodes + 127) / 128, 512, SMEM_SZ>>>(out, n_nodes);
}

// round 16
// speedup vs baseline: 1.0792x; 1.0558x over previous
#include <cuda_runtime.h>
#include <cuda_fp16.h>
#include <cstdint>

#define NREL 8
#define F    128
#define NMAX 100000
#define EMAX 1600000
#define NBUCK (NMAX * NREL)

// Scratch (no allocation allowed)
__device__ __align__(16) __half g_Hh[(size_t)NREL * NMAX * F];  // 204.8 MB
__device__ __align__(16) __half g_fh[(size_t)NMAX * F];         // 25.6 MB fp16 feat
__device__ __align__(16) __half g_wh[NREL * F * F];  // transposed: [r][n][k]
__device__ int g_cnt[NBUCK + 1];   // histogram -> block-local offsets -> local ends
__device__ int g_eidx[EMAX];       // src per edge, bucket-sorted
__device__ int g_bsum[1024];       // per-1024-chunk base offsets

// ---------------------------------------------------------------------------
// Fused setup: zero histogram, weight [r][k][n] -> fp16 [r][n][k],
// feat fp32 -> fp16 (4 elems/thread, vectorized)
// ---------------------------------------------------------------------------
__global__ void setup_kernel(const float* __restrict__ feat,
                             const float* __restrict__ wgt,
                             int n_feat4, int n_w, int nb) {
    int i = blockIdx.x * blockDim.x + threadIdx.x;
    if (i < n_feat4) {
        float4 v = reinterpret_cast<const float4*>(feat)[i];
        __half2 h01 = __halves2half2(__float2half_rn(v.x), __float2half_rn(v.y));
        __half2 h23 = __halves2half2(__float2half_rn(v.z), __float2half_rn(v.w));
        uint2 u;
        u.x = *reinterpret_cast<uint32_t*>(&h01);
        u.y = *reinterpret_cast<uint32_t*>(&h23);
        reinterpret_cast<uint2*>(g_fh)[i] = u;
    }
    if (i < n_w) {
        int r = i >> 14, rem = i & 16383, k = rem >> 7, nn = rem & 127;
        g_wh[r * 16384 + nn * 128 + k] = __float2half_rn(wgt[i]);
    }
    if (i <= nb) g_cnt[i] = 0;
}

// ---------------------------------------------------------------------------
// Counting sort by key = et*n_nodes + dst; 4 edges per thread for atomic MLP.
// ---------------------------------------------------------------------------
__global__ void hist_kernel(const int* __restrict__ dst,
                            const int* __restrict__ et, int E, int n_nodes) {
    int i = (blockIdx.x * blockDim.x + threadIdx.x) * 4;
    if (i + 3 < E) {
        int4 d = *reinterpret_cast<const int4*>(dst + i);
        int4 t = *reinterpret_cast<const int4*>(et + i);
        atomicAdd(&g_cnt[t.x * n_nodes + d.x], 1);
        atomicAdd(&g_cnt[t.y * n_nodes + d.y], 1);
        atomicAdd(&g_cnt[t.z * n_nodes + d.z], 1);
        atomicAdd(&g_cnt[t.w * n_nodes + d.w], 1);
    } else {
        for (int e = i; e < E; e++)
            atomicAdd(&g_cnt[et[e] * n_nodes + dst[e]], 1);
    }
}

// Pass 1: per-block (1024) exclusive scan in place; block totals -> g_bsum
__global__ void __launch_bounds__(1024) scan1_kernel(int n) {
    const int tid = threadIdx.x, lane = tid & 31, wid = tid >> 5;
    __shared__ int wsum[32];
    int i = blockIdx.x * 1024 + tid;
    int x = (i < n) ? g_cnt[i] : 0;
    int v = x;
#pragma unroll
    for (int d = 1; d < 32; d <<= 1) {
        int t = __shfl_up_sync(0xFFFFFFFFu, v, d);
        if (lane >= d) v += t;
    }
    if (lane == 31) wsum[wid] = v;
    __syncthreads();
    if (wid == 0) {
        int s = wsum[lane];
        int sv = s;
#pragma unroll
        for (int d = 1; d < 32; d <<= 1) {
            int t = __shfl_up_sync(0xFFFFFFFFu, sv, d);
            if (lane >= d) sv += t;
        }
        wsum[lane] = sv - s;
    }
    __syncthreads();
    if (i < n) g_cnt[i] = wsum[wid] + v - x;   // block-local exclusive
    if (tid == 1023) g_bsum[blockIdx.x] = wsum[31] + v;
}

// Pass 2: single-block exclusive scan of the <=1024 block totals (in place)
__global__ void __launch_bounds__(1024) scan2_kernel(int nblk) {
    const int tid = threadIdx.x, lane = tid & 31, wid = tid >> 5;
    __shared__ int wsum[32];
    int x = (tid < nblk) ? g_bsum[tid] : 0;
    int v = x;
#pragma unroll
    for (int d = 1; d < 32; d <<= 1) {
        int t = __shfl_up_sync(0xFFFFFFFFu, v, d);
        if (lane >= d) v += t;
    }
    if (lane == 31) wsum[wid] = v;
    __syncthreads();
    if (wid == 0) {
        int s = wsum[lane];
        int sv = s;
#pragma unroll
        for (int d = 1; d < 32; d <<= 1) {
            int t = __shfl_up_sync(0xFFFFFFFFu, sv, d);
            if (lane >= d) sv += t;
        }
        wsum[lane] = sv - s;
    }
    __syncthreads();
    if (tid < nblk) g_bsum[tid] = wsum[wid] + v - x;
}

// Fill: final position = local atomicAdd + chunk base; 4 edges per thread.
__global__ void fill_kernel(const int* __restrict__ src,
                            const int* __restrict__ dst,
                            const int* __restrict__ et, int E, int n_nodes) {
    int i = (blockIdx.x * blockDim.x + threadIdx.x) * 4;
    if (i + 3 < E) {
        int4 s = *reinterpret_cast<const int4*>(src + i);
        int4 d = *reinterpret_cast<const int4*>(dst + i);
        int4 t = *reinterpret_cast<const int4*>(et + i);
        int k0 = t.x * n_nodes + d.x, k1 = t.y * n_nodes + d.y;
        int k2 = t.z * n_nodes + d.z, k3 = t.w * n_nodes + d.w;
        int p0 = atomicAdd(&g_cnt[k0], 1) + g_bsum[k0 >> 10];
        int p1 = atomicAdd(&g_cnt[k1], 1) + g_bsum[k1 >> 10];
        int p2 = atomicAdd(&g_cnt[k2], 1) + g_bsum[k2 >> 10];
        int p3 = atomicAdd(&g_cnt[k3], 1) + g_bsum[k3 >> 10];
        g_eidx[p0] = s.x; g_eidx[p1] = s.y; g_eidx[p2] = s.z; g_eidx[p3] = s.w;
    } else {
        for (int e = i; e < E; e++) {
            int key = et[e] * n_nodes + dst[e];
            int p = atomicAdd(&g_cnt[key], 1) + g_bsum[key >> 10];
            g_eidx[p] = src[e];
        }
    }
}

// ---------------------------------------------------------------------------
// Aggregate: one warp per 4 CONSECUTIVE buckets (contiguous edge range).
// fp16 feat gather (256 B/row, L2-resident), fp32 accumulate.
// ---------------------------------------------------------------------------
__global__ void aggregate_kernel(int nb) {
    int w = (blockIdx.x * blockDim.x + threadIdx.x) >> 5;
    int lane = threadIdx.x & 31;
    int base = w * 4;
    if (base >= nb) return;

    // lane-parallel bounds: lane l in 0..4 loads end(base-1+l); end(-1)=0
    int kk = base - 1 + lane;
    int bnd = 0;
    if (lane < 5 && kk >= 0) bnd = g_cnt[kk] + g_bsum[kk >> 10];
    int e0 = __shfl_sync(0xFFFFFFFFu, bnd, 0);
    int e1 = __shfl_sync(0xFFFFFFFFu, bnd, 1);
    int e2 = __shfl_sync(0xFFFFFFFFu, bnd, 2);
    int e3 = __shfl_sync(0xFFFFFFFFu, bnd, 3);
    int e4 = __shfl_sync(0xFFFFFFFFu, bnd, 4);

    float4 a0 = make_float4(0.f, 0.f, 0.f, 0.f);
    float4 a1 = a0, a2 = a0, a3 = a0;

    for (int c = e0; c < e4; c += 8) {
        int s[8];
#pragma unroll
        for (int t = 0; t < 8; t++)
            s[t] = (c + t < e4) ? g_eidx[c + t] : -1;
        uint2 f[8];
#pragma unroll
        for (int t = 0; t < 8; t++)
            f[t] = (s[t] >= 0)
                ? *reinterpret_cast<const uint2*>(g_fh + (size_t)s[t] * F + lane * 4)
                : make_uint2(0u, 0u);
#pragma unroll
        for (int t = 0; t < 8; t++) {
            int j = c + t;
            if (j >= e4) break;           // warp-uniform
            float2 lo = __half22float2(*reinterpret_cast<__half2*>(&f[t].x));
            float2 hi = __half22float2(*reinterpret_cast<__half2*>(&f[t].y));
            if (j < e1)      { a0.x += lo.x; a0.y += lo.y; a0.z += hi.x; a0.w += hi.y; }
            else if (j < e2) { a1.x += lo.x; a1.y += lo.y; a1.z += hi.x; a1.w += hi.y; }
            else if (j < e3) { a2.x += lo.x; a2.y += lo.y; a2.z += hi.x; a2.w += hi.y; }
            else             { a3.x += lo.x; a3.y += lo.y; a3.z += hi.x; a3.w += hi.y; }
        }
    }

    // write 4 consecutive H rows (fp16)
#pragma unroll
    for (int i = 0; i < 4; i++) {
        float4 a = (i == 0) ? a0 : (i == 1) ? a1 : (i == 2) ? a2 : a3;
        __half2 h01 = __halves2half2(__float2half_rn(a.x), __float2half_rn(a.y));
        __half2 h23 = __halves2half2(__float2half_rn(a.z), __float2half_rn(a.w));
        uint2 u;
        u.x = *reinterpret_cast<uint32_t*>(&h01);
        u.y = *reinterpret_cast<uint32_t*>(&h23);
        *reinterpret_cast<uint2*>(g_Hh + (size_t)(base + i) * F + lane * 4) = u;
    }
}

// ---------------------------------------------------------------------------
// Legacy-pipe GEMM building blocks
// ---------------------------------------------------------------------------
__device__ __forceinline__ uint32_t smem_u32(const void* p) {
    uint32_t a;
    asm("{ .reg .u64 t; cvta.to.shared.u64 t, %1; cvt.u32.u64 %0, t; }" : "=r"(a) : "l"(p));
    return a;
}

__device__ __forceinline__ void mma16816(float c[4], const uint32_t a[4],
                                         const uint32_t b0, const uint32_t b1) {
    asm volatile(
        "mma.sync.aligned.m16n8k16.row.col.f32.f16.f16.f32 "
        "{%0,%1,%2,%3}, {%4,%5,%6,%7}, {%8,%9}, {%0,%1,%2,%3};"
        : "+f"(c[0]), "+f"(c[1]), "+f"(c[2]), "+f"(c[3])
        : "r"(a[0]), "r"(a[1]), "r"(a[2]), "r"(a[3]), "r"(b0), "r"(b1));
}

#define LDSM_X4(r, addr) \
    asm volatile("ldmatrix.sync.aligned.m8n8.x4.shared.b16 {%0,%1,%2,%3}, [%4];" \
                 : "=r"((r)[0]), "=r"((r)[1]), "=r"((r)[2]), "=r"((r)[3]) : "r"(addr))

#define PITCH_B 272
#define TILE_SZ (128 * PITCH_B)   // 34816 B

__device__ __forceinline__ void cpa_tile(uint32_t s_base, const __half* g,
                                         int valid_rows, int tid) {
    const char* gc = reinterpret_cast<const char*>(g);
#pragma unroll
    for (int it = 0; it < 4; it++) {
        int i = tid + it * 512;
        int m = i >> 4, c = i & 15;
        uint32_t s = s_base + m * PITCH_B + c * 16;
        const char* src = gc + m * 256 + c * 16;
        int sz = (m < valid_rows) ? 16 : 0;
        asm volatile("cp.async.cg.shared.global [%0], [%1], 16, %2;"
                     :: "r"(s), "l"(src), "r"(sz) : "memory");
    }
}

// SMEM map: A x2 buffers, B x2 buffers
#define OFF_A0 0u
#define OFF_A1 34816u
#define OFF_B0 69632u
#define OFF_B1 104448u
#define SMEM_SZ 139264

// ---------------------------------------------------------------------------
// GEMM: per CTA one 128-row dst tile; loop 8 relations with A=H_r, B=W_r;
// accumulate across relations in registers; write out once.
// ---------------------------------------------------------------------------
__global__ void __launch_bounds__(512, 1) gemm_kernel(float* __restrict__ out,
                                                      int n_nodes) {
    extern __shared__ __align__(128) char smem[];
    const uint32_t sb = smem_u32(smem);
    const int tid = threadIdx.x, wid = tid >> 5, lane = tid & 31;
    const int m0 = blockIdx.x * 128;
    const int valid = n_nodes - m0;

    // Prologue: relation 0 into buffer 0
    cpa_tile(sb + OFF_A0, g_Hh + (size_t)m0 * F, valid, tid);
    cpa_tile(sb + OFF_B0, g_wh, 128, tid);
    asm volatile("cp.async.commit_group;" ::: "memory");

    const int wm = (wid >> 1) * 16;
    const int wn = (wid & 1) * 64;
    const uint32_t a_off =
        (uint32_t)((wm + (lane & 15)) * PITCH_B + ((lane >> 4) * 8) * 2);
    const int b_row = (lane & 7) + ((lane >> 3) & 1) * 8;
    const uint32_t b_koff = (uint32_t)(((lane >> 4) * 8) * 2);

    float acc[8][4];
#pragma unroll
    for (int i = 0; i < 8; i++)
#pragma unroll
        for (int j = 0; j < 4; j++) acc[i][j] = 0.f;

    for (int q = 0; q < NREL; q++) {
        if (q < 7) {  // prefetch next relation into the other buffer
            const int nb1 = (q + 1) & 1;
            cpa_tile(sb + (nb1 ? OFF_A1 : OFF_A0),
                     g_Hh + ((size_t)(q + 1) * n_nodes + m0) * F, valid, tid);
            cpa_tile(sb + (nb1 ? OFF_B1 : OFF_B0),
                     g_wh + (size_t)(q + 1) * F * F, 128, tid);
            asm volatile("cp.async.commit_group;" ::: "memory");
            asm volatile("cp.async.wait_group 1;" ::: "memory");
        } else {
            asm volatile("cp.async.wait_group 0;" ::: "memory");
        }
        __syncthreads();

        const uint32_t ab = sb + ((q & 1) ? OFF_A1 : OFF_A0);
        const uint32_t bb = sb + ((q & 1) ? OFF_B1 : OFF_B0);

#pragma unroll
        for (int kk = 0; kk < 8; kk++) {
            const uint32_t k2 = (uint32_t)(kk * 32);
            uint32_t ah[4];
            LDSM_X4(ah, ab + a_off + k2);
#pragma unroll
            for (int nb = 0; nb < 4; nb++) {
                const uint32_t baddr =
                    bb + (uint32_t)((wn + nb * 16 + b_row) * PITCH_B) + b_koff + k2;
                uint32_t bh[4];
                LDSM_X4(bh, baddr);
                mma16816(acc[nb * 2],     ah, bh[0], bh[2]);
                mma16816(acc[nb * 2 + 1], ah, bh[1], bh[3]);
            }
        }
        __syncthreads();  // all warps done with buf (q&1) before refill
    }

    // Epilogue: single write of the relation-summed tile
    const int r0 = wm + (lane >> 2);
    const bool ok0 = (m0 + r0) < n_nodes;
    const bool ok1 = (m0 + r0 + 8) < n_nodes;
    float* cp = out + (size_t)m0 * F;
#pragma unroll
    for (int ns = 0; ns < 8; ns++) {
        const int col = wn + ns * 8 + (lane & 3) * 2;
        if (ok0) *(float2*)&cp[(size_t)r0 * F + col] =
            make_float2(acc[ns][0], acc[ns][1]);
        if (ok1) *(float2*)&cp[(size_t)(r0 + 8) * F + col] =
            make_float2(acc[ns][2], acc[ns][3]);
    }
}

// ---------------------------------------------------------------------------
extern "C" void kernel_launch(void* const* d_in, const int* in_sizes, int n_in,
                              void* d_out, int out_size) {
    const float* feat   = (const float*)d_in[0];
    const float* weight = (const float*)d_in[1];
    const int*   src    = (const int*)d_in[2];
    const int*   dst    = (const int*)d_in[3];
    const int*   et     = (const int*)d_in[4];

    const int n_nodes = in_sizes[0] / F;
    const int n_feat4 = in_sizes[0] / 4;      // 3.2M float4 groups
    const int n_w     = in_sizes[1];
    const int E       = in_sizes[2];
    float* out = (float*)d_out;

    const int nb = n_nodes * NREL;            // 800K buckets
    const int nblk = (nb + 1023) / 1024;      // scan blocks (<=1024)

    // Setup: feat fp16, weights fp16 transposed, zero histogram
    int setup_n = n_feat4 > (nb + 1) ? n_feat4 : (nb + 1);
    setup_kernel<<<(setup_n + 255) / 256, 256>>>(feat, weight, n_feat4, n_w, nb);

    // Counting sort by (et, dst)
    hist_kernel<<<(E / 4 + 255) / 256, 256>>>(dst, et, E, n_nodes);
    scan1_kernel<<<nblk, 1024>>>(nb);
    scan2_kernel<<<1, 1024>>>(nblk);
    fill_kernel<<<(E / 4 + 255) / 256, 256>>>(src, dst, et, E, n_nodes);

    // Aggregate fp16 feat into H rows: 4 consecutive buckets per warp
    aggregate_kernel<<<(nb * 8 + 255) / 256, 256>>>(nb);

    // Fused relation-sum GEMM: out = sum_r H_r @ W_r
    cudaFuncSetAttribute(gemm_kernel,
                         cudaFuncAttributeMaxDynamicSharedMemorySize, SMEM_SZ);
    gemm_kernel<<<(n_nodes + 127) / 128, 512, SMEM_SZ>>>(out, n_nodes);
}